// round 16
// baseline (speedup 1.0000x reference)
#include <cuda_runtime.h>
#include <cuda_fp16.h>
#include <cstdint>

#define BB   2
#define SS   2048
#define DIMM 4096
#define NHH  32
#define NKVV 8
#define HDD  128

// ---------------------------------------------------------------------------
// Scratch (device globals; no allocation allowed)
// ---------------------------------------------------------------------------
__device__ __align__(16) __half g_xh[16777216];
__device__ __align__(16) __half g_xl[16777216];
__device__ __align__(16) __half g_wqh[16777216];
__device__ __align__(16) __half g_wkh[4194304];
__device__ __align__(16) __half g_wvh[4194304];
__device__ __align__(16) __half g_woh[16777216];
__device__ __align__(16) __half g_qh[16777216];
__device__ __align__(16) __half g_kh[4194304];
__device__ __align__(16) __half g_vh[4194304];
__device__ __align__(16) __half g_oh[16777216];

// ---------------------------------------------------------------------------
__device__ __forceinline__ uint32_t smem_u32(const void* p) {
    uint32_t a;
    asm("{ .reg .u64 t; cvta.to.shared.u64 t, %1; cvt.u32.u64 %0, t; }"
        : "=r"(a) : "l"(p));
    return a;
}

__device__ __forceinline__ void mma_f16(float* c, const uint32_t* a,
                                        const uint32_t* b) {
    asm volatile(
        "mma.sync.aligned.m16n8k16.row.col.f32.f16.f16.f32 "
        "{%0,%1,%2,%3}, {%4,%5,%6,%7}, {%8,%9}, {%0,%1,%2,%3};"
        : "+f"(c[0]), "+f"(c[1]), "+f"(c[2]), "+f"(c[3])
        : "r"(a[0]), "r"(a[1]), "r"(a[2]), "r"(a[3]), "r"(b[0]), "r"(b[1]));
}

__device__ __forceinline__ void ldsm4(uint32_t* r, uint32_t addr) {
    asm volatile(
        "ldmatrix.sync.aligned.m8n8.x4.shared.b16 {%0,%1,%2,%3}, [%4];"
        : "=r"(r[0]), "=r"(r[1]), "=r"(r[2]), "=r"(r[3]) : "r"(addr));
}
__device__ __forceinline__ void ldsm4t(uint32_t* r, uint32_t addr) {
    asm volatile(
        "ldmatrix.sync.aligned.m8n8.x4.trans.shared.b16 {%0,%1,%2,%3}, [%4];"
        : "=r"(r[0]), "=r"(r[1]), "=r"(r[2]), "=r"(r[3]) : "r"(addr));
}
#define CP_ASYNC16(dst, src) \
    asm volatile("cp.async.cg.shared.global [%0], [%1], 16;" :: "r"(dst), "l"(src))

// ---------------------------------------------------------------------------
// Split fp32 -> fp16 hi + lo   /   fp32 -> fp16 hi only
// ---------------------------------------------------------------------------
__global__ void split2_kernel(const float* __restrict__ in,
                              __half* __restrict__ hi,
                              __half* __restrict__ lo, int n4)
{
    int i = blockIdx.x * blockDim.x + threadIdx.x;
    if (i >= n4) return;
    float4 v = *(const float4*)(in + (size_t)i * 4);
    __half h0 = __float2half_rn(v.x), h1 = __float2half_rn(v.y);
    __half h2 = __float2half_rn(v.z), h3 = __float2half_rn(v.w);
    ((__half2*)hi)[i * 2]     = __halves2half2(h0, h1);
    ((__half2*)hi)[i * 2 + 1] = __halves2half2(h2, h3);
    ((__half2*)lo)[i * 2]     = __halves2half2(
        __float2half_rn(v.x - __half2float(h0)),
        __float2half_rn(v.y - __half2float(h1)));
    ((__half2*)lo)[i * 2 + 1] = __halves2half2(
        __float2half_rn(v.z - __half2float(h2)),
        __float2half_rn(v.w - __half2float(h3)));
}

__global__ void tohalf_kernel(const float* __restrict__ in,
                              __half* __restrict__ hi, int n4)
{
    int i = blockIdx.x * blockDim.x + threadIdx.x;
    if (i >= n4) return;
    float4 v = *(const float4*)(in + (size_t)i * 4);
    ((__half2*)hi)[i * 2] =
        __halves2half2(__float2half_rn(v.x), __float2half_rn(v.y));
    ((__half2*)hi)[i * 2 + 1] =
        __halves2half2(__float2half_rn(v.z), __float2half_rn(v.w));
}

// ---------------------------------------------------------------------------
// PERSISTENT mma.sync GEMM, fp16 A (hi; + lo input term only for Q segment):
//   mode==1 (Q): acc = Ah*B + Al*B       otherwise: acc = Ah*B
// Grid = 2 x #SM CTAs; each grid-strides over (mb, nb) tiles (nb-major).
// CTA tile 128x128, BK=32, 3-stage cp.async pipeline ({Ah,Al,B} per stage),
// 8 warps (2x4), warp tile 64x32. 2 CTAs/SM pinned.
// 3 output segments (by nb) so Q, K, V project in ONE launch.
// Epilogue modes: 0 = fp32 C; 1 = rope+scale+hi; 2 = rope+hi; 3 = hi
// ---------------------------------------------------------------------------
#define LDA   40
#define A_PART (128 * LDA * 2)            // 10240
#define STAGE_BYTES (3 * A_PART)          // 30720: Ah | Al | B
#define GEMM_SMEM (3 * STAGE_BYTES)       // 92160

__device__ __forceinline__ void gemm_copy_stage(
    const __half* __restrict__ Ah, const __half* __restrict__ Al,
    const __half* __restrict__ Bp, int use_lo,
    int K, int m0, int n0, int kk, uint32_t st, int tid)
{
    int row = tid >> 1;
    int cc  = (tid & 1) * 16;
    uint32_t d = st + (uint32_t)(row * LDA + cc) * 2;
    const __half* ga = Ah + (size_t)(m0 + row) * K + kk + cc;
    CP_ASYNC16(d, ga);
    CP_ASYNC16(d + 16, ga + 8);
    if (use_lo) {
        const __half* gl = Al + (size_t)(m0 + row) * K + kk + cc;
        CP_ASYNC16(d + A_PART, gl);
        CP_ASYNC16(d + A_PART + 16, gl + 8);
    }
    const __half* gb = Bp + (size_t)(n0 + row) * K + kk + cc;
    CP_ASYNC16(d + 2 * A_PART, gb);
    CP_ASYNC16(d + 2 * A_PART + 16, gb + 8);
}

__global__ __launch_bounds__(256, 2) void gemm_mma(
    const __half* __restrict__ Ah, const __half* __restrict__ Al,
    const __half* __restrict__ B1, const __half* __restrict__ B2,
    const __half* __restrict__ B3, int ns1, int ns2, int n_nb,
    float* __restrict__ C, __half* __restrict__ H1,
    __half* __restrict__ H2, __half* __restrict__ H3,
    const float* __restrict__ fc, const float* __restrict__ fs,
    int M, int N1, int N2, int K,
    int mode1, int mode2, int mode3, float scale)
{
    extern __shared__ char dsm[];
    const uint32_t sb = smem_u32(dsm);
    const int tid  = threadIdx.x;
    const int wid  = tid >> 5;
    const int lane = tid & 31;
    const int wm = wid >> 2;       // 0..1 (64 rows each)
    const int wn = wid & 3;        // 0..3 (32 cols each)

    const int a_lrow = wm * 64 + (lane & 15);
    const int a_koff = (lane >> 4) * 8;
    const int b_g    = lane >> 3;
    const int b_nrow = wn * 32 + (lane & 7) + ((b_g >> 1) * 8);
    const int b_koff = (b_g & 1) * 8;

    const int n_it = K >> 5;
    const int n_tiles = n_nb * (M >> 7);

    for (int t = blockIdx.x; t < n_tiles; t += gridDim.x) {
        const int m0 = (t / n_nb) * 128;
        int nb = t - (t / n_nb) * n_nb;

        // segment select (Q / K / V or single-segment O)
        const __half* Bp_sel;
        __half* H;
        int mode, Nout;
        if (nb < ns1)            { Bp_sel = B1; H = H1; mode = mode1; Nout = N1; }
        else if (nb < ns1 + ns2) { Bp_sel = B2; H = H2; mode = mode2; Nout = N2; nb -= ns1; }
        else                     { Bp_sel = B3; H = H3; mode = mode3; Nout = N2; nb -= ns1 + ns2; }
        const int n0 = nb * 128;
        const int use_lo = (mode == 1);

        // All warps must be done reading the previous tile's smem before the
        // new prologue overwrites stages 0/1.
        __syncthreads();

        float acc[4][4][4];
#pragma unroll
        for (int mi = 0; mi < 4; mi++)
#pragma unroll
            for (int ni = 0; ni < 4; ni++)
#pragma unroll
                for (int q = 0; q < 4; q++) acc[mi][ni][q] = 0.0f;

#pragma unroll
        for (int s = 0; s < 2; s++) {
            gemm_copy_stage(Ah, Al, Bp_sel, use_lo, K, m0, n0, s * 32,
                            sb + s * STAGE_BYTES, tid);
            asm volatile("cp.async.commit_group;" ::: "memory");
        }

#pragma unroll 1
        for (int it = 0; it < n_it; it++) {
            asm volatile("cp.async.wait_group 1;" ::: "memory");
            __syncthreads();

            {
                int nx = it + 2;
                if (nx < n_it)
                    gemm_copy_stage(Ah, Al, Bp_sel, use_lo, K, m0, n0, nx << 5,
                                    sb + (nx % 3) * STAGE_BYTES, tid);
                asm volatile("cp.async.commit_group;" ::: "memory");
            }

            const uint32_t sAh = sb + (it % 3) * STAGE_BYTES;
            const uint32_t sAl = sAh + A_PART;
            const uint32_t sB  = sAh + 2 * A_PART;

#pragma unroll
            for (int ks = 0; ks < 2; ks++) {
                const int koff = ks * 16;
                uint32_t afh[4][4], afl[4][4], bf[4][2];
#pragma unroll
                for (int mi = 0; mi < 4; mi++) {
                    uint32_t ao =
                        (uint32_t)((a_lrow + mi * 16) * LDA + koff + a_koff) * 2;
                    ldsm4(afh[mi], sAh + ao);
                    if (use_lo) ldsm4(afl[mi], sAl + ao);
                }
#pragma unroll
                for (int p = 0; p < 2; p++) {
                    uint32_t tt[4];
                    ldsm4(tt, sB + (uint32_t)((b_nrow + p * 16) * LDA + koff + b_koff) * 2);
                    bf[2 * p][0] = tt[0]; bf[2 * p][1] = tt[1];
                    bf[2 * p + 1][0] = tt[2]; bf[2 * p + 1][1] = tt[3];
                }
#pragma unroll
                for (int mi = 0; mi < 4; mi++)
#pragma unroll
                    for (int ni = 0; ni < 4; ni++)
                        mma_f16(acc[mi][ni], afh[mi], bf[ni]);
                if (use_lo) {
#pragma unroll
                    for (int mi = 0; mi < 4; mi++)
#pragma unroll
                        for (int ni = 0; ni < 4; ni++)
                            mma_f16(acc[mi][ni], afl[mi], bf[ni]);
                }
            }
        }

        // ---- epilogue ----
        auto epi = [&](int r, int c, float x, float y) {
            if (mode != 3) {  // rope (modes 1, 2); scale applied only in mode 1
                int s = r & (SS - 1);
                int i = (c & (HDD - 1)) >> 1;
                float cs = fc[s * 64 + i], sn = fs[s * 64 + i];
                float xr = x * cs - y * sn;
                float xi = x * sn + y * cs;
                if (mode == 1) { xr *= scale; xi *= scale; }
                x = xr;
                y = xi;
            }
            size_t idx = (size_t)r * Nout + c;
            *(__half2*)(H + idx) =
                __halves2half2(__float2half_rn(x), __float2half_rn(y));
        };

#pragma unroll
        for (int mi = 0; mi < 4; mi++) {
            int row = m0 + wm * 64 + mi * 16 + (lane >> 2);
#pragma unroll
            for (int ni = 0; ni < 4; ni++) {
                int col = n0 + wn * 32 + ni * 8 + (lane & 3) * 2;
                if (mode == 0) {
                    *(float2*)(C + (size_t)row * Nout + col) =
                        make_float2(acc[mi][ni][0], acc[mi][ni][1]);
                    *(float2*)(C + (size_t)(row + 8) * Nout + col) =
                        make_float2(acc[mi][ni][2], acc[mi][ni][3]);
                } else {
                    epi(row, col, acc[mi][ni][0], acc[mi][ni][1]);
                    epi(row + 8, col, acc[mi][ni][2], acc[mi][ni][3]);
                }
            }
        }
    }
}

// ---------------------------------------------------------------------------
// Flash attention, mma.sync, causal GQA. 128 q-rows/CTA, 8 warps.
// 1-term QK (Qh*Kh), 2-term PV (Ph*Vh + Pl*Vh).
// K/V double-buffered. Epilogue writes fp16 hi.   [R15, unchanged]
// ---------------------------------------------------------------------------
#define LDT 136
#define KV_STAGE 34816
#define FLASH_SMEM 69632

__device__ __forceinline__ uint32_t pack_p(float x, float y, float* rx, float* ry) {
    __half hx = __float2half_rn(x), hy = __float2half_rn(y);
    *rx = x - __half2float(hx);
    *ry = y - __half2float(hy);
    __half2 h2 = __halves2half2(hx, hy);
    return *(uint32_t*)&h2;
}
__device__ __forceinline__ uint32_t pack_h(float x, float y) {
    __half2 h2 = __halves2half2(__float2half_rn(x), __float2half_rn(y));
    return *(uint32_t*)&h2;
}

__global__ __launch_bounds__(256) void flash_mma()
{
    extern __shared__ char sm[];
    const uint32_t sb = smem_u32(sm);
    const int tid = threadIdx.x, lane = tid & 31, w = tid >> 5;
    const int qt = gridDim.x - 1 - blockIdx.x;
    const int h = blockIdx.y, b = blockIdx.z, hk = h >> 2;
    const int q0 = qt * 128;

    const uint32_t sQh = sb;

    {
        const __half* qh = g_qh + ((size_t)(b * SS + q0) * NHH + h) * HDD;
        for (int c = tid; c < 2048; c += 256) {
            int row = c >> 4, c8 = (c & 15) * 8;
            uint32_t off = (uint32_t)(row * LDT + c8) * 2;
            CP_ASYNC16(sQh + off, qh + (size_t)row * (NHH * HDD) + c8);
        }
        asm volatile("cp.async.commit_group;" ::: "memory");
        asm volatile("cp.async.wait_group 0;" ::: "memory");
        __syncthreads();
    }
    uint32_t qf[8][4];
    {
        const int arow = w * 16 + (lane & 15);
        const int akoff = (lane >> 4) * 8;
#pragma unroll
        for (int ks = 0; ks < 8; ks++)
            ldsm4(qf[ks], sQh + (uint32_t)(arow * LDT + ks * 16 + akoff) * 2);
    }
    __syncthreads();

    float m0 = -1e30f, m1 = -1e30f, l0 = 0.0f, l1 = 0.0f;
    float O[16][4];
#pragma unroll
    for (int i = 0; i < 16; i++)
#pragma unroll
        for (int q = 0; q < 4; q++) O[i][q] = 0.0f;

    const int bg = lane >> 3;
    const int b_nrow = (lane & 7) + ((bg >> 1) << 3);
    const int b_koff = (bg & 1) * 8;
    const int vr   = (lane & 7) + ((bg & 1) << 3);
    const int v_hd = (lane >> 4) * 8;

    auto load_tile = [&](int kt, int stg) {
        size_t base = ((size_t)(b * SS + kt * 64) * NKVV + hk) * HDD;
        uint32_t sK = sb + stg * KV_STAGE;
        uint32_t sV = sK + 17408;
        for (int c = tid; c < 1024; c += 256) {
            int row = c >> 4, c8 = (c & 15) * 8;
            uint32_t off = (uint32_t)(row * LDT + c8) * 2;
            size_t g = base + (size_t)row * (NKVV * HDD) + c8;
            CP_ASYNC16(sK + off, g_kh + g);
            CP_ASYNC16(sV + off, g_vh + g);
        }
        asm volatile("cp.async.commit_group;" ::: "memory");
    };

    const int nkt = 2 * qt + 2;
    load_tile(0, 0);

    for (int kt = 0; kt < nkt; kt++) {
        const int cur = kt & 1;
        __syncthreads();
        if (kt + 1 < nkt) {
            load_tile(kt + 1, cur ^ 1);
            asm volatile("cp.async.wait_group 1;" ::: "memory");
        } else {
            asm volatile("cp.async.wait_group 0;" ::: "memory");
        }
        __syncthreads();

        const uint32_t sK = sb + cur * KV_STAGE;
        const uint32_t sV = sK + 17408;

        float S[8][4];
#pragma unroll
        for (int nt = 0; nt < 8; nt++)
#pragma unroll
            for (int q = 0; q < 4; q++) S[nt][q] = 0.0f;

#pragma unroll
        for (int ks = 0; ks < 8; ks++) {
#pragma unroll
            for (int p = 0; p < 4; p++) {
                uint32_t kb[4];
                ldsm4(kb, sK + (uint32_t)((p * 16 + b_nrow) * LDT + ks * 16 + b_koff) * 2);
                mma_f16(S[2 * p], qf[ks], kb);
                mma_f16(S[2 * p + 1], qf[ks], kb + 2);
            }
        }

        const int r0g = q0 + w * 16 + (lane >> 2);
        const int r1g = r0g + 8;
        if (kt >= 2 * qt) {
            int cb = kt * 64 + (lane & 3) * 2;
#pragma unroll
            for (int nt = 0; nt < 8; nt++) {
                int c0 = cb + nt * 8;
                if (c0 > r0g)     S[nt][0] = -1e30f;
                if (c0 + 1 > r0g) S[nt][1] = -1e30f;
                if (c0 > r1g)     S[nt][2] = -1e30f;
                if (c0 + 1 > r1g) S[nt][3] = -1e30f;
            }
        }

        float mx0 = -1e30f, mx1 = -1e30f;
#pragma unroll
        for (int nt = 0; nt < 8; nt++) {
            mx0 = fmaxf(mx0, fmaxf(S[nt][0], S[nt][1]));
            mx1 = fmaxf(mx1, fmaxf(S[nt][2], S[nt][3]));
        }
        mx0 = fmaxf(mx0, __shfl_xor_sync(0xffffffffu, mx0, 1));
        mx0 = fmaxf(mx0, __shfl_xor_sync(0xffffffffu, mx0, 2));
        mx1 = fmaxf(mx1, __shfl_xor_sync(0xffffffffu, mx1, 1));
        mx1 = fmaxf(mx1, __shfl_xor_sync(0xffffffffu, mx1, 2));
        float mn0 = fmaxf(m0, mx0), mn1 = fmaxf(m1, mx1);
        float al0 = __expf(m0 - mn0), al1 = __expf(m1 - mn1);
        m0 = mn0; m1 = mn1;
        float rs0 = 0.0f, rs1 = 0.0f;
#pragma unroll
        for (int nt = 0; nt < 8; nt++) {
            S[nt][0] = __expf(S[nt][0] - m0);
            S[nt][1] = __expf(S[nt][1] - m0);
            S[nt][2] = __expf(S[nt][2] - m1);
            S[nt][3] = __expf(S[nt][3] - m1);
            rs0 += S[nt][0] + S[nt][1];
            rs1 += S[nt][2] + S[nt][3];
        }
        rs0 += __shfl_xor_sync(0xffffffffu, rs0, 1);
        rs0 += __shfl_xor_sync(0xffffffffu, rs0, 2);
        rs1 += __shfl_xor_sync(0xffffffffu, rs1, 1);
        rs1 += __shfl_xor_sync(0xffffffffu, rs1, 2);
        l0 = l0 * al0 + rs0;
        l1 = l1 * al1 + rs1;
#pragma unroll
        for (int i = 0; i < 16; i++) {
            O[i][0] *= al0; O[i][1] *= al0;
            O[i][2] *= al1; O[i][3] *= al1;
        }

#pragma unroll
        for (int kp = 0; kp < 4; kp++) {
            uint32_t ph[4], pl[4];
            float rx, ry;
            ph[0] = pack_p(S[2 * kp][0], S[2 * kp][1], &rx, &ry);
            pl[0] = pack_h(rx, ry);
            ph[1] = pack_p(S[2 * kp][2], S[2 * kp][3], &rx, &ry);
            pl[1] = pack_h(rx, ry);
            ph[2] = pack_p(S[2 * kp + 1][0], S[2 * kp + 1][1], &rx, &ry);
            pl[2] = pack_h(rx, ry);
            ph[3] = pack_p(S[2 * kp + 1][2], S[2 * kp + 1][3], &rx, &ry);
            pl[3] = pack_h(rx, ry);
#pragma unroll
            for (int np = 0; np < 8; np++) {
                uint32_t vb[4];
                ldsm4t(vb, sV + (uint32_t)((kp * 16 + vr) * LDT + np * 16 + v_hd) * 2);
                mma_f16(O[2 * np], ph, vb);
                mma_f16(O[2 * np + 1], ph, vb + 2);
                mma_f16(O[2 * np], pl, vb);
                mma_f16(O[2 * np + 1], pl, vb + 2);
            }
        }
    }

    float i0 = 1.0f / l0, i1 = 1.0f / l1;
    int r0g = q0 + w * 16 + (lane >> 2);
    size_t idx0 = ((size_t)(b * SS + r0g) * NHH + h) * HDD + (lane & 3) * 2;
    size_t idx1 = idx0 + (size_t)8 * NHH * HDD;
#pragma unroll
    for (int nt = 0; nt < 16; nt++) {
        *(__half2*)(g_oh + idx0 + nt * 8) =
            __halves2half2(__float2half_rn(O[nt][0] * i0),
                           __float2half_rn(O[nt][1] * i0));
        *(__half2*)(g_oh + idx1 + nt * 8) =
            __halves2half2(__float2half_rn(O[nt][2] * i1),
                           __float2half_rn(O[nt][3] * i1));
    }
}

// ---------------------------------------------------------------------------
extern "C" void kernel_launch(void* const* d_in, const int* in_sizes, int n_in,
                              void* d_out, int out_size)
{
    const float* x  = (const float*)d_in[0];
    const float* wq = (const float*)d_in[1];
    const float* wk = (const float*)d_in[2];
    const float* wv = (const float*)d_in[3];
    const float* wo = (const float*)d_in[4];
    const float* fc = (const float*)d_in[5];
    const float* fs = (const float*)d_in[6];
    float* out = (float*)d_out;

    __half *xh, *xl, *wqh, *wkh, *wvh, *woh, *qh, *kh, *vh, *oh;
    cudaGetSymbolAddress((void**)&xh, g_xh);
    cudaGetSymbolAddress((void**)&xl, g_xl);
    cudaGetSymbolAddress((void**)&wqh, g_wqh);
    cudaGetSymbolAddress((void**)&wkh, g_wkh);
    cudaGetSymbolAddress((void**)&wvh, g_wvh);
    cudaGetSymbolAddress((void**)&woh, g_woh);
    cudaGetSymbolAddress((void**)&qh, g_qh);
    cudaGetSymbolAddress((void**)&kh, g_kh);
    cudaGetSymbolAddress((void**)&vh, g_vh);
    cudaGetSymbolAddress((void**)&oh, g_oh);

    int nsm = 148;
    cudaDeviceGetAttribute(&nsm, cudaDevAttrMultiProcessorCount, 0);
    const int pgrid = 2 * nsm;             // 2 CTAs/SM persistent

    const int M = BB * SS;                 // 4096
    const int NBIG = 16777216 / 4;
    const int NSM  = 4194304 / 4;
    const float qscale = 0.08838834764831845f;

    split2_kernel<<<(NBIG + 255) / 256, 256>>>(x, xh, xl, NBIG);
    tohalf_kernel<<<(NBIG + 255) / 256, 256>>>(wq, wqh, NBIG);
    tohalf_kernel<<<(NSM + 255) / 256, 256>>>(wk, wkh, NSM);
    tohalf_kernel<<<(NSM + 255) / 256, 256>>>(wv, wvh, NSM);
    tohalf_kernel<<<(NBIG + 255) / 256, 256>>>(wo, woh, NBIG);

    cudaFuncSetAttribute(gemm_mma, cudaFuncAttributeMaxDynamicSharedMemorySize,
                         GEMM_SMEM);

    // Q + K + V projections in ONE persistent launch (48 n-blocks x 32 m-blocks):
    //   nb [0,32):  Q  (2-term input) -> rope + qscale + hi
    //   nb [32,40): K  (1-term)       -> rope + hi
    //   nb [40,48): V  (1-term)       -> hi
    gemm_mma<<<pgrid, 256, GEMM_SMEM>>>(
        xh, xl, wqh, wkh, wvh, 32, 8, 48, nullptr, qh, kh, vh, fc, fs,
        M, 4096, 1024, DIMM, 1, 2, 3, qscale);

    cudaFuncSetAttribute(flash_mma, cudaFuncAttributeMaxDynamicSharedMemorySize,
                         FLASH_SMEM);
    flash_mma<<<dim3(SS / 128, NHH, BB), 256, FLASH_SMEM>>>();

    // Output projection: hi-only (1-term), fp32 out, persistent (32 n-blocks)
    gemm_mma<<<pgrid, 256, GEMM_SMEM>>>(
        oh, oh, woh, woh, woh, 32, 0, 32, out, nullptr, nullptr, nullptr,
        fc, fs, M, 4096, 1024, DIMM, 0, 0, 0, 1.0f);
}

// round 17
// speedup vs baseline: 1.0205x; 1.0205x over previous
#include <cuda_runtime.h>
#include <cuda_fp16.h>
#include <cstdint>

#define BB   2
#define SS   2048
#define DIMM 4096
#define NHH  32
#define NKVV 8
#define HDD  128

// ---------------------------------------------------------------------------
// Scratch (device globals; no allocation allowed)
// ---------------------------------------------------------------------------
__device__ __align__(16) __half g_xh[16777216];
__device__ __align__(16) __half g_xl[16777216];
__device__ __align__(16) __half g_wqh[16777216];
__device__ __align__(16) __half g_wkh[4194304];
__device__ __align__(16) __half g_wvh[4194304];
__device__ __align__(16) __half g_woh[16777216];
__device__ __align__(16) __half g_qh[16777216];
__device__ __align__(16) __half g_kh[4194304];
__device__ __align__(16) __half g_vh[4194304];
__device__ __align__(16) __half g_oh[16777216];

// ---------------------------------------------------------------------------
__device__ __forceinline__ uint32_t smem_u32(const void* p) {
    uint32_t a;
    asm("{ .reg .u64 t; cvta.to.shared.u64 t, %1; cvt.u32.u64 %0, t; }"
        : "=r"(a) : "l"(p));
    return a;
}

__device__ __forceinline__ void mma_f16(float* c, const uint32_t* a,
                                        const uint32_t* b) {
    asm volatile(
        "mma.sync.aligned.m16n8k16.row.col.f32.f16.f16.f32 "
        "{%0,%1,%2,%3}, {%4,%5,%6,%7}, {%8,%9}, {%0,%1,%2,%3};"
        : "+f"(c[0]), "+f"(c[1]), "+f"(c[2]), "+f"(c[3])
        : "r"(a[0]), "r"(a[1]), "r"(a[2]), "r"(a[3]), "r"(b[0]), "r"(b[1]));
}

__device__ __forceinline__ void ldsm4(uint32_t* r, uint32_t addr) {
    asm volatile(
        "ldmatrix.sync.aligned.m8n8.x4.shared.b16 {%0,%1,%2,%3}, [%4];"
        : "=r"(r[0]), "=r"(r[1]), "=r"(r[2]), "=r"(r[3]) : "r"(addr));
}
__device__ __forceinline__ void ldsm4t(uint32_t* r, uint32_t addr) {
    asm volatile(
        "ldmatrix.sync.aligned.m8n8.x4.trans.shared.b16 {%0,%1,%2,%3}, [%4];"
        : "=r"(r[0]), "=r"(r[1]), "=r"(r[2]), "=r"(r[3]) : "r"(addr));
}
#define CP_ASYNC16(dst, src) \
    asm volatile("cp.async.cg.shared.global [%0], [%1], 16;" :: "r"(dst), "l"(src))

// ---------------------------------------------------------------------------
// Merged conversion: ONE launch does x->hi/lo split + wq/wk/wv/wo -> hi.
// Segment layout (in float4 units):
//   [0, NB)            : x  -> xh, xl (split)
//   [NB, 2NB)          : wq -> wqh
//   [2NB, 2NB+NS)      : wk -> wkh
//   [2NB+NS, 2NB+2NS)  : wv -> wvh
//   [2NB+2NS, 3NB+2NS) : wo -> woh
// ---------------------------------------------------------------------------
#define NB4 4194304            // 4096*4096/4
#define NS4 1048576            // 1024*4096/4

__global__ void convert_all(const float* __restrict__ x,
                            const float* __restrict__ wq,
                            const float* __restrict__ wk,
                            const float* __restrict__ wv,
                            const float* __restrict__ wo,
                            __half* __restrict__ xh, __half* __restrict__ xl,
                            __half* __restrict__ wqh, __half* __restrict__ wkh,
                            __half* __restrict__ wvh, __half* __restrict__ woh)
{
    int i = blockIdx.x * blockDim.x + threadIdx.x;
    const int total = 3 * NB4 + 2 * NS4;
    if (i >= total) return;

    const float* src;
    __half* hi;
    int idx = i;
    bool split = false;
    if (idx < NB4)                  { src = x;  hi = xh; split = true; }
    else if ((idx -= NB4) < NB4)    { src = wq; hi = wqh; }
    else if ((idx -= NB4) < NS4)    { src = wk; hi = wkh; }
    else if ((idx -= NS4) < NS4)    { src = wv; hi = wvh; }
    else                            { idx -= NS4; src = wo; hi = woh; }

    float4 v = *(const float4*)(src + (size_t)idx * 4);
    __half h0 = __float2half_rn(v.x), h1 = __float2half_rn(v.y);
    __half h2 = __float2half_rn(v.z), h3 = __float2half_rn(v.w);
    ((__half2*)hi)[idx * 2]     = __halves2half2(h0, h1);
    ((__half2*)hi)[idx * 2 + 1] = __halves2half2(h2, h3);
    if (split) {
        ((__half2*)xl)[idx * 2]     = __halves2half2(
            __float2half_rn(v.x - __half2float(h0)),
            __float2half_rn(v.y - __half2float(h1)));
        ((__half2*)xl)[idx * 2 + 1] = __halves2half2(
            __float2half_rn(v.z - __half2float(h2)),
            __float2half_rn(v.w - __half2float(h3)));
    }
}

// fp32 -> fp16 hi only (for flash O output conversion reuse if needed)
__global__ void tohalf_kernel(const float* __restrict__ in,
                              __half* __restrict__ hi, int n4)
{
    int i = blockIdx.x * blockDim.x + threadIdx.x;
    if (i >= n4) return;
    float4 v = *(const float4*)(in + (size_t)i * 4);
    ((__half2*)hi)[i * 2] =
        __halves2half2(__float2half_rn(v.x), __float2half_rn(v.y));
    ((__half2*)hi)[i * 2 + 1] =
        __halves2half2(__float2half_rn(v.z), __float2half_rn(v.w));
}

// ---------------------------------------------------------------------------
// mma.sync GEMM, fp16 A (hi, + lo input term only for Q segment), K-major:
//   mode==1 (Q): acc = Ah*B + Al*B       otherwise: acc = Ah*B
// CTA tile 128x128, BK=32, 3-stage cp.async pipeline ({Ah,Al,B} per stage),
// 8 warps (2x4), warp tile 64x32. 2 CTAs/SM pinned.  [R15, unchanged]
// 3 output segments (by n-block) so Q, K, V project in ONE launch.
// Epilogue modes: 0 = fp32 C; 1 = rope+scale+hi; 2 = rope+hi; 3 = hi
// ---------------------------------------------------------------------------
#define LDA   40
#define A_PART (128 * LDA * 2)            // 10240
#define STAGE_BYTES (3 * A_PART)          // 30720: Ah | Al | B
#define GEMM_SMEM (3 * STAGE_BYTES)       // 92160

__device__ __forceinline__ void gemm_copy_stage(
    const __half* __restrict__ Ah, const __half* __restrict__ Al,
    const __half* __restrict__ Bp, int use_lo,
    int K, int m0, int n0, int kk, uint32_t st, int tid)
{
    int row = tid >> 1;
    int cc  = (tid & 1) * 16;
    uint32_t d = st + (uint32_t)(row * LDA + cc) * 2;
    const __half* ga = Ah + (size_t)(m0 + row) * K + kk + cc;
    CP_ASYNC16(d, ga);
    CP_ASYNC16(d + 16, ga + 8);
    if (use_lo) {
        const __half* gl = Al + (size_t)(m0 + row) * K + kk + cc;
        CP_ASYNC16(d + A_PART, gl);
        CP_ASYNC16(d + A_PART + 16, gl + 8);
    }
    const __half* gb = Bp + (size_t)(n0 + row) * K + kk + cc;
    CP_ASYNC16(d + 2 * A_PART, gb);
    CP_ASYNC16(d + 2 * A_PART + 16, gb + 8);
}

__global__ __launch_bounds__(256, 2) void gemm_mma(
    const __half* __restrict__ Ah, const __half* __restrict__ Al,
    const __half* __restrict__ B1, const __half* __restrict__ B2,
    const __half* __restrict__ B3, int ns1, int ns2,
    float* __restrict__ C, __half* __restrict__ H1,
    __half* __restrict__ H2, __half* __restrict__ H3,
    const float* __restrict__ fc, const float* __restrict__ fs,
    int M, int N1, int N2, int K,
    int mode1, int mode2, int mode3, float scale)
{
    extern __shared__ char dsm[];
    const uint32_t sb = smem_u32(dsm);
    const int tid  = threadIdx.x;
    const int wid  = tid >> 5;
    const int lane = tid & 31;
    const int wm = wid >> 2;       // 0..1 (64 rows each)
    const int wn = wid & 3;        // 0..3 (32 cols each)
    const int m0 = blockIdx.y * 128;

    // segment select (Q / K / V or single-segment O)
    const __half* Bp_sel;
    __half* H;
    int mode, Nout;
    int nb = blockIdx.x;
    if (nb < ns1)            { Bp_sel = B1; H = H1; mode = mode1; Nout = N1; }
    else if (nb < ns1 + ns2) { Bp_sel = B2; H = H2; mode = mode2; Nout = N2; nb -= ns1; }
    else                     { Bp_sel = B3; H = H3; mode = mode3; Nout = N2; nb -= ns1 + ns2; }
    const int n0 = nb * 128;
    const int use_lo = (mode == 1);   // only the Q projection keeps the input lo term

    const int n_it = K >> 5;

    float acc[4][4][4];
#pragma unroll
    for (int mi = 0; mi < 4; mi++)
#pragma unroll
        for (int ni = 0; ni < 4; ni++)
#pragma unroll
            for (int q = 0; q < 4; q++) acc[mi][ni][q] = 0.0f;

    const int a_lrow = wm * 64 + (lane & 15);
    const int a_koff = (lane >> 4) * 8;
    const int b_g    = lane >> 3;
    const int b_nrow = wn * 32 + (lane & 7) + ((b_g >> 1) * 8);
    const int b_koff = (b_g & 1) * 8;

#pragma unroll
    for (int s = 0; s < 2; s++) {
        gemm_copy_stage(Ah, Al, Bp_sel, use_lo, K, m0, n0, s * 32,
                        sb + s * STAGE_BYTES, tid);
        asm volatile("cp.async.commit_group;" ::: "memory");
    }

#pragma unroll 1
    for (int it = 0; it < n_it; it++) {
        asm volatile("cp.async.wait_group 1;" ::: "memory");
        __syncthreads();

        {
            int nx = it + 2;
            if (nx < n_it)
                gemm_copy_stage(Ah, Al, Bp_sel, use_lo, K, m0, n0, nx << 5,
                                sb + (nx % 3) * STAGE_BYTES, tid);
            asm volatile("cp.async.commit_group;" ::: "memory");
        }

        const uint32_t sAh = sb + (it % 3) * STAGE_BYTES;
        const uint32_t sAl = sAh + A_PART;
        const uint32_t sB  = sAh + 2 * A_PART;

#pragma unroll
        for (int ks = 0; ks < 2; ks++) {
            const int koff = ks * 16;
            uint32_t afh[4][4], afl[4][4], bf[4][2];
#pragma unroll
            for (int mi = 0; mi < 4; mi++) {
                uint32_t ao = (uint32_t)((a_lrow + mi * 16) * LDA + koff + a_koff) * 2;
                ldsm4(afh[mi], sAh + ao);
                if (use_lo) ldsm4(afl[mi], sAl + ao);
            }
#pragma unroll
            for (int p = 0; p < 2; p++) {
                uint32_t t[4];
                ldsm4(t, sB + (uint32_t)((b_nrow + p * 16) * LDA + koff + b_koff) * 2);
                bf[2 * p][0] = t[0]; bf[2 * p][1] = t[1];
                bf[2 * p + 1][0] = t[2]; bf[2 * p + 1][1] = t[3];
            }
#pragma unroll
            for (int mi = 0; mi < 4; mi++)
#pragma unroll
                for (int ni = 0; ni < 4; ni++)
                    mma_f16(acc[mi][ni], afh[mi], bf[ni]);
            if (use_lo) {
#pragma unroll
                for (int mi = 0; mi < 4; mi++)
#pragma unroll
                    for (int ni = 0; ni < 4; ni++)
                        mma_f16(acc[mi][ni], afl[mi], bf[ni]);
            }
        }
    }

    // ---- epilogue ----
    auto epi = [&](int r, int c, float x, float y) {
        if (mode != 3) {  // rope (modes 1, 2); scale applied only in mode 1
            int s = r & (SS - 1);
            int i = (c & (HDD - 1)) >> 1;
            float cs = fc[s * 64 + i], sn = fs[s * 64 + i];
            float xr = x * cs - y * sn;
            float xi = x * sn + y * cs;
            if (mode == 1) { xr *= scale; xi *= scale; }
            x = xr;
            y = xi;
        }
        size_t idx = (size_t)r * Nout + c;
        *(__half2*)(H + idx) =
            __halves2half2(__float2half_rn(x), __float2half_rn(y));
    };

#pragma unroll
    for (int mi = 0; mi < 4; mi++) {
        int row = m0 + wm * 64 + mi * 16 + (lane >> 2);
#pragma unroll
        for (int ni = 0; ni < 4; ni++) {
            int col = n0 + wn * 32 + ni * 8 + (lane & 3) * 2;
            if (mode == 0) {
                *(float2*)(C + (size_t)row * Nout + col) =
                    make_float2(acc[mi][ni][0], acc[mi][ni][1]);
                *(float2*)(C + (size_t)(row + 8) * Nout + col) =
                    make_float2(acc[mi][ni][2], acc[mi][ni][3]);
            } else {
                epi(row, col, acc[mi][ni][0], acc[mi][ni][1]);
                epi(row + 8, col, acc[mi][ni][2], acc[mi][ni][3]);
            }
        }
    }
}

// ---------------------------------------------------------------------------
// Flash attention, mma.sync, causal GQA. 128 q-rows/CTA, 8 warps.
// 1-term QK (Qh*Kh), 2-term PV (Ph*Vh + Pl*Vh).
// K/V double-buffered. Epilogue writes fp16 hi.   [R15, unchanged]
// ---------------------------------------------------------------------------
#define LDT 136
#define KV_STAGE 34816
#define FLASH_SMEM 69632

__device__ __forceinline__ uint32_t pack_p(float x, float y, float* rx, float* ry) {
    __half hx = __float2half_rn(x), hy = __float2half_rn(y);
    *rx = x - __half2float(hx);
    *ry = y - __half2float(hy);
    __half2 h2 = __halves2half2(hx, hy);
    return *(uint32_t*)&h2;
}
__device__ __forceinline__ uint32_t pack_h(float x, float y) {
    __half2 h2 = __halves2half2(__float2half_rn(x), __float2half_rn(y));
    return *(uint32_t*)&h2;
}

__global__ __launch_bounds__(256) void flash_mma()
{
    extern __shared__ char sm[];
    const uint32_t sb = smem_u32(sm);
    const int tid = threadIdx.x, lane = tid & 31, w = tid >> 5;
    const int qt = gridDim.x - 1 - blockIdx.x;
    const int h = blockIdx.y, b = blockIdx.z, hk = h >> 2;
    const int q0 = qt * 128;

    const uint32_t sQh = sb;

    {
        const __half* qh = g_qh + ((size_t)(b * SS + q0) * NHH + h) * HDD;
        for (int c = tid; c < 2048; c += 256) {
            int row = c >> 4, c8 = (c & 15) * 8;
            uint32_t off = (uint32_t)(row * LDT + c8) * 2;
            CP_ASYNC16(sQh + off, qh + (size_t)row * (NHH * HDD) + c8);
        }
        asm volatile("cp.async.commit_group;" ::: "memory");
        asm volatile("cp.async.wait_group 0;" ::: "memory");
        __syncthreads();
    }
    uint32_t qf[8][4];
    {
        const int arow = w * 16 + (lane & 15);
        const int akoff = (lane >> 4) * 8;
#pragma unroll
        for (int ks = 0; ks < 8; ks++)
            ldsm4(qf[ks], sQh + (uint32_t)(arow * LDT + ks * 16 + akoff) * 2);
    }
    __syncthreads();

    float m0 = -1e30f, m1 = -1e30f, l0 = 0.0f, l1 = 0.0f;
    float O[16][4];
#pragma unroll
    for (int i = 0; i < 16; i++)
#pragma unroll
        for (int q = 0; q < 4; q++) O[i][q] = 0.0f;

    const int bg = lane >> 3;
    const int b_nrow = (lane & 7) + ((bg >> 1) << 3);
    const int b_koff = (bg & 1) * 8;
    const int vr   = (lane & 7) + ((bg & 1) << 3);
    const int v_hd = (lane >> 4) * 8;

    auto load_tile = [&](int kt, int stg) {
        size_t base = ((size_t)(b * SS + kt * 64) * NKVV + hk) * HDD;
        uint32_t sK = sb + stg * KV_STAGE;
        uint32_t sV = sK + 17408;
        for (int c = tid; c < 1024; c += 256) {
            int row = c >> 4, c8 = (c & 15) * 8;
            uint32_t off = (uint32_t)(row * LDT + c8) * 2;
            size_t g = base + (size_t)row * (NKVV * HDD) + c8;
            CP_ASYNC16(sK + off, g_kh + g);
            CP_ASYNC16(sV + off, g_vh + g);
        }
        asm volatile("cp.async.commit_group;" ::: "memory");
    };

    const int nkt = 2 * qt + 2;
    load_tile(0, 0);

    for (int kt = 0; kt < nkt; kt++) {
        const int cur = kt & 1;
        __syncthreads();
        if (kt + 1 < nkt) {
            load_tile(kt + 1, cur ^ 1);
            asm volatile("cp.async.wait_group 1;" ::: "memory");
        } else {
            asm volatile("cp.async.wait_group 0;" ::: "memory");
        }
        __syncthreads();

        const uint32_t sK = sb + cur * KV_STAGE;
        const uint32_t sV = sK + 17408;

        float S[8][4];
#pragma unroll
        for (int nt = 0; nt < 8; nt++)
#pragma unroll
            for (int q = 0; q < 4; q++) S[nt][q] = 0.0f;

#pragma unroll
        for (int ks = 0; ks < 8; ks++) {
#pragma unroll
            for (int p = 0; p < 4; p++) {
                uint32_t kb[4];
                ldsm4(kb, sK + (uint32_t)((p * 16 + b_nrow) * LDT + ks * 16 + b_koff) * 2);
                mma_f16(S[2 * p], qf[ks], kb);
                mma_f16(S[2 * p + 1], qf[ks], kb + 2);
            }
        }

        const int r0g = q0 + w * 16 + (lane >> 2);
        const int r1g = r0g + 8;
        if (kt >= 2 * qt) {
            int cb = kt * 64 + (lane & 3) * 2;
#pragma unroll
            for (int nt = 0; nt < 8; nt++) {
                int c0 = cb + nt * 8;
                if (c0 > r0g)     S[nt][0] = -1e30f;
                if (c0 + 1 > r0g) S[nt][1] = -1e30f;
                if (c0 > r1g)     S[nt][2] = -1e30f;
                if (c0 + 1 > r1g) S[nt][3] = -1e30f;
            }
        }

        float mx0 = -1e30f, mx1 = -1e30f;
#pragma unroll
        for (int nt = 0; nt < 8; nt++) {
            mx0 = fmaxf(mx0, fmaxf(S[nt][0], S[nt][1]));
            mx1 = fmaxf(mx1, fmaxf(S[nt][2], S[nt][3]));
        }
        mx0 = fmaxf(mx0, __shfl_xor_sync(0xffffffffu, mx0, 1));
        mx0 = fmaxf(mx0, __shfl_xor_sync(0xffffffffu, mx0, 2));
        mx1 = fmaxf(mx1, __shfl_xor_sync(0xffffffffu, mx1, 1));
        mx1 = fmaxf(mx1, __shfl_xor_sync(0xffffffffu, mx1, 2));
        float mn0 = fmaxf(m0, mx0), mn1 = fmaxf(m1, mx1);
        float al0 = __expf(m0 - mn0), al1 = __expf(m1 - mn1);
        m0 = mn0; m1 = mn1;
        float rs0 = 0.0f, rs1 = 0.0f;
#pragma unroll
        for (int nt = 0; nt < 8; nt++) {
            S[nt][0] = __expf(S[nt][0] - m0);
            S[nt][1] = __expf(S[nt][1] - m0);
            S[nt][2] = __expf(S[nt][2] - m1);
            S[nt][3] = __expf(S[nt][3] - m1);
            rs0 += S[nt][0] + S[nt][1];
            rs1 += S[nt][2] + S[nt][3];
        }
        rs0 += __shfl_xor_sync(0xffffffffu, rs0, 1);
        rs0 += __shfl_xor_sync(0xffffffffu, rs0, 2);
        rs1 += __shfl_xor_sync(0xffffffffu, rs1, 1);
        rs1 += __shfl_xor_sync(0xffffffffu, rs1, 2);
        l0 = l0 * al0 + rs0;
        l1 = l1 * al1 + rs1;
#pragma unroll
        for (int i = 0; i < 16; i++) {
            O[i][0] *= al0; O[i][1] *= al0;
            O[i][2] *= al1; O[i][3] *= al1;
        }

#pragma unroll
        for (int kp = 0; kp < 4; kp++) {
            uint32_t ph[4], pl[4];
            float rx, ry;
            ph[0] = pack_p(S[2 * kp][0], S[2 * kp][1], &rx, &ry);
            pl[0] = pack_h(rx, ry);
            ph[1] = pack_p(S[2 * kp][2], S[2 * kp][3], &rx, &ry);
            pl[1] = pack_h(rx, ry);
            ph[2] = pack_p(S[2 * kp + 1][0], S[2 * kp + 1][1], &rx, &ry);
            pl[2] = pack_h(rx, ry);
            ph[3] = pack_p(S[2 * kp + 1][2], S[2 * kp + 1][3], &rx, &ry);
            pl[3] = pack_h(rx, ry);
#pragma unroll
            for (int np = 0; np < 8; np++) {
                uint32_t vb[4];
                ldsm4t(vb, sV + (uint32_t)((kp * 16 + vr) * LDT + np * 16 + v_hd) * 2);
                mma_f16(O[2 * np], ph, vb);
                mma_f16(O[2 * np + 1], ph, vb + 2);
                mma_f16(O[2 * np], pl, vb);
                mma_f16(O[2 * np + 1], pl, vb + 2);
            }
        }
    }

    float i0 = 1.0f / l0, i1 = 1.0f / l1;
    int r0g = q0 + w * 16 + (lane >> 2);
    size_t idx0 = ((size_t)(b * SS + r0g) * NHH + h) * HDD + (lane & 3) * 2;
    size_t idx1 = idx0 + (size_t)8 * NHH * HDD;
#pragma unroll
    for (int nt = 0; nt < 16; nt++) {
        *(__half2*)(g_oh + idx0 + nt * 8) =
            __halves2half2(__float2half_rn(O[nt][0] * i0),
                           __float2half_rn(O[nt][1] * i0));
        *(__half2*)(g_oh + idx1 + nt * 8) =
            __halves2half2(__float2half_rn(O[nt][2] * i1),
                           __float2half_rn(O[nt][3] * i1));
    }
}

// ---------------------------------------------------------------------------
extern "C" void kernel_launch(void* const* d_in, const int* in_sizes, int n_in,
                              void* d_out, int out_size)
{
    const float* x  = (const float*)d_in[0];
    const float* wq = (const float*)d_in[1];
    const float* wk = (const float*)d_in[2];
    const float* wv = (const float*)d_in[3];
    const float* wo = (const float*)d_in[4];
    const float* fc = (const float*)d_in[5];
    const float* fs = (const float*)d_in[6];
    float* out = (float*)d_out;

    __half *xh, *xl, *wqh, *wkh, *wvh, *woh, *qh, *kh, *vh, *oh;
    cudaGetSymbolAddress((void**)&xh, g_xh);
    cudaGetSymbolAddress((void**)&xl, g_xl);
    cudaGetSymbolAddress((void**)&wqh, g_wqh);
    cudaGetSymbolAddress((void**)&wkh, g_wkh);
    cudaGetSymbolAddress((void**)&wvh, g_wvh);
    cudaGetSymbolAddress((void**)&woh, g_woh);
    cudaGetSymbolAddress((void**)&qh, g_qh);
    cudaGetSymbolAddress((void**)&kh, g_kh);
    cudaGetSymbolAddress((void**)&vh, g_vh);
    cudaGetSymbolAddress((void**)&oh, g_oh);

    const int M = BB * SS;                 // 4096
    const int NBIG = 16777216 / 4;
    const float qscale = 0.08838834764831845f;

    // ONE merged conversion launch (x split + 4 weight tohalfs)
    const int conv_total = 3 * NB4 + 2 * NS4;
    convert_all<<<(conv_total + 255) / 256, 256>>>(
        x, wq, wk, wv, wo, xh, xl, wqh, wkh, wvh, woh);

    cudaFuncSetAttribute(gemm_mma, cudaFuncAttributeMaxDynamicSharedMemorySize,
                         GEMM_SMEM);

    // Q + K + V projections in ONE launch:
    //   blocks [0,32):  Q  (2-term input) -> rope + qscale + hi
    //   blocks [32,40): K  (1-term)       -> rope + hi
    //   blocks [40,48): V  (1-term)       -> hi
    gemm_mma<<<dim3(48, 32), 256, GEMM_SMEM>>>(
        xh, xl, wqh, wkh, wvh, 32, 8, nullptr, qh, kh, vh, fc, fs,
        M, 4096, 1024, DIMM, 1, 2, 3, qscale);

    cudaFuncSetAttribute(flash_mma, cudaFuncAttributeMaxDynamicSharedMemorySize,
                         FLASH_SMEM);
    flash_mma<<<dim3(SS / 128, NHH, BB), 256, FLASH_SMEM>>>();

    // Output projection: hi-only (1-term), fp32 out
    gemm_mma<<<dim3(32, 32), 256, GEMM_SMEM>>>(
        oh, oh, woh, woh, woh, 32, 0, out, nullptr, nullptr, nullptr,
        fc, fs, M, 4096, 1024, DIMM, 0, 0, 0, 1.0f);
}